// round 17
// baseline (speedup 1.0000x reference)
#include <cuda_runtime.h>
#include <cuda_fp16.h>
#include <cstdint>
#include <math.h>

// Problem dims
#define B_DIM 128
#define S_DIM 1024
#define I_DIM 256
#define H_DIM 512
#define G4H   2048
#define O_DIM 10

// Recurrence partition: 128 persistent CTAs = 8 batch parts x 16 k parts
#define NCTA   128
#define PPARTS 8
#define QPARTS 16
#define GRP    16           // CTAs per barrier group (one batch part)
#define BP (B_DIM/PPARTS)   // 16 batch rows per CTA
#define KP (H_DIM/QPARTS)   // 32 h-columns per CTA

#define W2_PITCH 260        // 256 half2 + 4 pad -> conflict-free LDSM (row shift 4 banks)
#define GS2 132             // gate smem pitch (floats)

// smem: W slice [128][260] u32(half2) + h tile [16][260] u32 + gate slabs [4][16][132] f32
#define SMEM_LSTM_BYTES ((128*W2_PITCH + 16*W2_PITCH)*4 + 4*16*GS2*4)
// xproj: double-buffered A/B half tiles [2][128][36] u32 each
#define SMEM_XP_BYTES (4 * 128 * 36 * 4)

// Scratch (device globals: the sanctioned no-alloc workaround)
__device__ float g_xp[(size_t)S_DIM * B_DIM * G4H];        // 1 GB: x_proj [s][b][g]
__device__ __align__(256) __half g_x16[(size_t)B_DIM * S_DIM * I_DIM];  // fp16 x
__device__ __align__(256) __half g_w16[(size_t)G4H * I_DIM];            // fp16 W_ih
__device__ __align__(256) __half g_h[2][B_DIM * H_DIM];    // ping-pong h (fp16)
__device__ unsigned long long g_bar8[64];                  // 8 group barriers (monotonic)
__device__ uint32_t g_flag[PPARTS * QPARTS * 32];          // per-CTA step flags, 128B apart

__device__ __forceinline__ void cpa16(uint32_t smem_dst, const void* gsrc) {
    asm volatile("cp.async.cg.shared.global [%0], [%1], 16;\n"
                 :: "r"(smem_dst), "l"(gsrc));
}
__device__ __forceinline__ void cpa_commit() {
    asm volatile("cp.async.commit_group;\n" ::: "memory");
}
template <int N>
__device__ __forceinline__ void cpa_wait() {
    asm volatile("cp.async.wait_group %0;\n" :: "n"(N) : "memory");
}
__device__ __forceinline__ uint32_t ld_acq(const uint32_t* p) {
    uint32_t v;
    asm volatile("ld.acquire.gpu.global.b32 %0, [%1];" : "=r"(v) : "l"(p) : "memory");
    return v;
}
__device__ __forceinline__ void st_rel(uint32_t* p, uint32_t v) {
    asm volatile("st.release.gpu.global.b32 [%0], %1;" :: "l"(p), "r"(v) : "memory");
}
__device__ __forceinline__ void ldsm4(uint32_t& r0, uint32_t& r1, uint32_t& r2,
                                      uint32_t& r3, uint32_t a) {
    asm volatile("ldmatrix.sync.aligned.m8n8.x4.shared.b16 {%0,%1,%2,%3}, [%4];"
                 : "=r"(r0), "=r"(r1), "=r"(r2), "=r"(r3) : "r"(a));
}

// fp16 mma with fp32 accumulate
__device__ __forceinline__ void mma_f16(float& d0, float& d1, float& d2, float& d3,
                                        uint32_t a0, uint32_t a1, uint32_t a2, uint32_t a3,
                                        uint32_t b0, uint32_t b1) {
    asm volatile(
        "mma.sync.aligned.m16n8k16.row.col.f32.f16.f16.f32 "
        "{%0,%1,%2,%3},{%4,%5,%6,%7},{%8,%9},{%0,%1,%2,%3};"
        : "+f"(d0), "+f"(d1), "+f"(d2), "+f"(d3)
        : "r"(a0), "r"(a1), "r"(a2), "r"(a3), "r"(b0), "r"(b1));
}

// ============================================================================
// Phase 0: fp16 pre-conversion of x and W_ih (RNE).
// ============================================================================
__global__ __launch_bounds__(256) void cvt_x_kernel(const float* __restrict__ x) {
    size_t i = (size_t)blockIdx.x * 256 + threadIdx.x;
    const float4* src = reinterpret_cast<const float4*>(x) + i * 2;
    float4 v0 = src[0], v1 = src[1];
    __half2 h0 = __floats2half2_rn(v0.x, v0.y);
    __half2 h1 = __floats2half2_rn(v0.z, v0.w);
    __half2 h2 = __floats2half2_rn(v1.x, v1.y);
    __half2 h3 = __floats2half2_rn(v1.z, v1.w);
    uint4 o;
    o.x = *reinterpret_cast<uint32_t*>(&h0);
    o.y = *reinterpret_cast<uint32_t*>(&h1);
    o.z = *reinterpret_cast<uint32_t*>(&h2);
    o.w = *reinterpret_cast<uint32_t*>(&h3);
    reinterpret_cast<uint4*>(g_x16)[i] = o;
}

__global__ __launch_bounds__(256) void cvt_w_kernel(const float* __restrict__ Wih) {
    size_t i = (size_t)blockIdx.x * 256 + threadIdx.x;
    float4 v = reinterpret_cast<const float4*>(Wih)[i];
    __half2 h0 = __floats2half2_rn(v.x, v.y);
    __half2 h1 = __floats2half2_rn(v.z, v.w);
    uint2 o;
    o.x = *reinterpret_cast<uint32_t*>(&h0);
    o.y = *reinterpret_cast<uint32_t*>(&h1);
    reinterpret_cast<uint2*>(g_w16)[i] = o;
}

// ============================================================================
// Phase 1: x_proj = x @ W_ih^T + b_ih + b_hh. fp16 m16n8k16, fp32 accum.
// CTA: fixed s, M=128 batch, N=128 gate cols, K=256 halves in 4 chunks.
// ============================================================================
__global__ __launch_bounds__(256) void xproj_kernel(
    const float* __restrict__ bih, const float* __restrict__ bhh) {
    extern __shared__ uint32_t smx[];
    const int s   = blockIdx.y;
    const int n0  = blockIdx.x * 128;
    const int tid = threadIdx.x;
    const int warp = tid >> 5, lane = tid & 31;
    const int gid = lane >> 2, tq = lane & 3;
    const int mw = warp >> 1, nw = warp & 1;   // 4 M-warps x 2 N-warps

    const uint32_t smx_base = (uint32_t)__cvta_generic_to_shared(smx);

    auto load_chunk = [&](int kc4, int buf) {
        int kc = kc4 * 64;
#pragma unroll
        for (int j = 0; j < 4; j++) {
            int id = tid + 256 * j;            // 0..1023
            int r  = id >> 3;                  // row 0..127
            int c  = id & 7;                   // 8-half group
            cpa16(smx_base + (buf * 128 * 36 + r * 36 + c * 4) * 4,
                  g_x16 + ((size_t)r * S_DIM + s) * I_DIM + kc + c * 8);
            cpa16(smx_base + ((2 + buf) * 128 * 36 + r * 36 + c * 4) * 4,
                  g_w16 + (size_t)(n0 + r) * I_DIM + kc + c * 8);
        }
    };

    float acc[2][8][4] = {};

    load_chunk(0, 0);
    cpa_commit();

    for (int kc4 = 0; kc4 < 4; kc4++) {
        int cur = kc4 & 1;
        if (kc4 < 3) {
            load_chunk(kc4 + 1, cur ^ 1);
            cpa_commit();
            cpa_wait<1>();
        } else {
            cpa_wait<0>();
        }
        __syncthreads();

        const uint32_t* As = smx + cur * 128 * 36;
        const uint32_t* Bs = smx + (2 + cur) * 128 * 36;
#pragma unroll
        for (int ks = 0; ks < 4; ks++) {        // 4 k16 steps per chunk
            int k2 = ks * 8;                    // half2 base
            uint32_t a[2][4];
#pragma unroll
            for (int mt = 0; mt < 2; mt++) {
                int m0 = mw * 32 + mt * 16;
                a[mt][0] = As[(m0 + gid) * 36 + k2 + tq];
                a[mt][1] = As[(m0 + gid + 8) * 36 + k2 + tq];
                a[mt][2] = As[(m0 + gid) * 36 + k2 + tq + 4];
                a[mt][3] = As[(m0 + gid + 8) * 36 + k2 + tq + 4];
            }
#pragma unroll
            for (int nt = 0; nt < 8; nt++) {
                int nn = nw * 64 + nt * 8;
                uint32_t b0 = Bs[(nn + gid) * 36 + k2 + tq];
                uint32_t b1 = Bs[(nn + gid) * 36 + k2 + tq + 4];
                mma_f16(acc[0][nt][0], acc[0][nt][1], acc[0][nt][2], acc[0][nt][3],
                        a[0][0], a[0][1], a[0][2], a[0][3], b0, b1);
                mma_f16(acc[1][nt][0], acc[1][nt][1], acc[1][nt][2], acc[1][nt][3],
                        a[1][0], a[1][1], a[1][2], a[1][3], b0, b1);
            }
        }
        __syncthreads();
    }

#pragma unroll
    for (int mt = 0; mt < 2; mt++) {
        int row = mw * 32 + mt * 16 + gid;       // batch row
#pragma unroll
        for (int nt = 0; nt < 8; nt++) {
            int col = n0 + nw * 64 + nt * 8 + tq * 2;
            float bs0 = bih[col]     + bhh[col];
            float bs1 = bih[col + 1] + bhh[col + 1];
            size_t r0 = ((size_t)s * B_DIM + row) * G4H + col;
            size_t r1 = ((size_t)s * B_DIM + row + 8) * G4H + col;
            g_xp[r0]     = acc[mt][nt][0] + bs0;
            g_xp[r0 + 1] = acc[mt][nt][1] + bs1;
            g_xp[r1]     = acc[mt][nt][2] + bs0;
            g_xp[r1 + 1] = acc[mt][nt][3] + bs1;
        }
    }
}

// ============================================================================
// Phase 2: persistent recurrence, fp16 m16n8k16 / fp32 accum. 8x16 partition.
// CTA (p,q): batch rows [p*16,+16), h-cols [q*32,+32) (x4 gates = 128 gate rows).
// 8 warps = 4 k-parts x 2 n-halves; warp: M=16, N=64, K-chunk=128.
// Incremental staging: per producer i (4 per pair): poll flag_i -> cp.async its
// 1KB slice immediately (loads overlap straggler waits). No pre-MMA CTA sync.
// ============================================================================
__global__ __launch_bounds__(256, 1) void lstm_kernel(const float* __restrict__ Whh) {
    extern __shared__ uint32_t sm[];
    uint32_t* Ws = sm;                                    // [128][260] half2
    uint32_t* hs = sm + 128 * W2_PITCH;                   // [16][260] half2
    float*    gs = (float*)(sm + (128 + 16) * W2_PITCH);  // [4][16][132]

    const int tid  = threadIdx.x;
    const int warp = tid >> 5, lane = tid & 31;
    const int gid  = lane >> 2, tq = lane & 3;
    const int kp = warp & 3;         // k-part: K range [kp*128, kp*128+128)
    const int nh = warp >> 2;        // n-half: N cols [nh*64, nh*64+64)
    const int pl = nh * 32 + lane;   // lane id within the kp warp pair (0..63)
    const int q = blockIdx.x & (QPARTS - 1);
    const int p = blockIdx.x >> 4;

    const uint32_t hs_base = (uint32_t)__cvta_generic_to_shared(hs);
    const uint32_t ws_base = (uint32_t)__cvta_generic_to_shared(Ws);
    uint32_t* myflag = &g_flag[(p * QPARTS + q) * 32];

    // ldmatrix lane offsets (u32 units), k-base added per step.
    // A (hs, m16k16): rows lane&15, +8-half col for lanes>=16.
    const uint32_t a_off = (uint32_t)((lane & 15) * W2_PITCH + ((lane >> 4) << 2));
    // B (Ws, n16k16 per x4): verified round-16 mapping, re-based for N=64/pair.
    const uint32_t b_row_base = (uint32_t)(nh * 64 + (lane & 7) + ((lane >> 4) << 3));
    const uint32_t b_col = ((lane >> 3) & 1) << 2;
    uint32_t b_off[4];
#pragma unroll
    for (int nt2 = 0; nt2 < 4; nt2++)
        b_off[nt2] = (b_row_base + nt2 * 16) * W2_PITCH + b_col;

    // Reset own flag for this launch (replay safety).
    if (tid == 0) *myflag = 0;

    // Load resident W_hh slice as half2 (RNE).
    // Ws row r (0..127): gate g=r>>5, col j=r&31 -> W_hh row g*512 + q*32 + j.
#pragma unroll
    for (int it = 0; it < 128; it++) {
        int id = tid + 256 * it;           // 0..32767
        int r  = id >> 8;                  // 0..127
        int c2 = id & 255;                 // half2 index 0..255
        int wr = (r >> 5) * H_DIM + q * KP + (r & 31);
        float f0 = Whh[(size_t)wr * H_DIM + 2 * c2];
        float f1 = Whh[(size_t)wr * H_DIM + 2 * c2 + 1];
        __half2 hv = __floats2half2_rn(f0, f1);
        Ws[r * W2_PITCH + c2] = *reinterpret_cast<uint32_t*>(&hv);
    }

    // One group barrier: all 16 CTAs' flag resets visible before any polling.
    __syncthreads();
    if (tid == 0) {
        __threadfence();
        unsigned long long* bar = &g_bar8[p * 8];
        unsigned long long ticket = atomicAdd(bar, 1ULL);
        unsigned long long target = (ticket / GRP + 1) * (unsigned long long)GRP;
        while (*(volatile unsigned long long*)bar < target) { }
        __threadfence();
    }
    __syncthreads();

    // Persistent c-state: thread owns (b,k) pairs tid and tid+256.
    float creg[2] = {0.f, 0.f};

    // Prefetch x_proj gate values for t=0.
    float xv[2][4];
    {
        const float* xps = g_xp + ((size_t)p * BP) * G4H;
#pragma unroll
        for (int r2 = 0; r2 < 2; r2++) {
            int pr = tid + r2 * 256;
            int bl = pr >> 5, kc = pr & 31;
#pragma unroll
            for (int g = 0; g < 4; g++)
                xv[r2][g] = xps[(size_t)bl * G4H + g * 512 + q * KP + kc];
        }
    }

    // Staging geometry: lane pl covers hs row pl>>2, 16B group (pl&3).
    const int st_r  = pl >> 2;          // 0..15
    const int st_c4 = (pl & 3) * 4;     // u32 col offset 0..12

    for (int t = 0; t < S_DIM; t++) {
        float acc[8][4] = {};
        if (t > 0) {
            const __half* hp = g_h[(t + 1) & 1] + (size_t)p * BP * H_DIM;
            // Incremental per-producer staging: poll, then load its 1KB slice.
#pragma unroll
            for (int i = 0; i < 4; i++) {
                const uint32_t* pf = &g_flag[(p * QPARTS + kp * 4 + i) * 32];
                while (ld_acq(pf) < (uint32_t)t) { }
                int qc = (kp * 4 + i) * 16;     // u32 col base of producer's slice
                cpa16(hs_base + (st_r * W2_PITCH + qc + st_c4) * 4,
                      hp + (size_t)st_r * H_DIM + 2 * (qc + st_c4));
                cpa_commit();
            }
            cpa_wait<0>();
            asm volatile("bar.sync %0, 64;" :: "r"(1 + kp) : "memory");

#pragma unroll
            for (int ks = 0; ks < 8; ks++) {
                uint32_t k0u = (uint32_t)(kp * 64 + ks * 8);
                uint32_t a[4];
                ldsm4(a[0], a[1], a[2], a[3], hs_base + (a_off + k0u) * 4);
#pragma unroll
                for (int nt2 = 0; nt2 < 4; nt2++) {
                    uint32_t bb[4];
                    ldsm4(bb[0], bb[1], bb[2], bb[3],
                          ws_base + (b_off[nt2] + k0u) * 4);
                    mma_f16(acc[nt2*2][0], acc[nt2*2][1], acc[nt2*2][2], acc[nt2*2][3],
                            a[0], a[1], a[2], a[3], bb[0], bb[1]);
                    mma_f16(acc[nt2*2+1][0], acc[nt2*2+1][1], acc[nt2*2+1][2], acc[nt2*2+1][3],
                            a[0], a[1], a[2], a[3], bb[2], bb[3]);
                }
            }
        }

        // Scatter k-part partials into slab kp (float2 stores).
        {
            float* gsp = gs + kp * 16 * GS2;
#pragma unroll
            for (int nt = 0; nt < 8; nt++) {
                int col = nh * 64 + nt * 8 + tq * 2;
                *reinterpret_cast<float2*>(gsp + gid * GS2 + col) =
                    make_float2(acc[nt][0], acc[nt][1]);
                *reinterpret_cast<float2*>(gsp + (gid + 8) * GS2 + col) =
                    make_float2(acc[nt][2], acc[nt][3]);
            }
        }

        // Prefetch next step's x_proj early (overlaps elementwise + publish).
        float xvn[2][4];
        if (t + 1 < S_DIM) {
            const float* xps = g_xp + ((size_t)(t + 1) * B_DIM + p * BP) * G4H;
#pragma unroll
            for (int r2 = 0; r2 < 2; r2++) {
                int pr = tid + r2 * 256;
                int bl = pr >> 5, kc = pr & 31;
#pragma unroll
                for (int g = 0; g < 4; g++)
                    xvn[r2][g] = xps[(size_t)bl * G4H + g * 512 + q * KP + kc];
            }
        }
        __syncthreads();

        // Elementwise: sum 4 k-slabs + x_proj, gate math, c update, h write (fp16 RNE).
        __half* hdst = g_h[t & 1];
#pragma unroll
        for (int r2 = 0; r2 < 2; r2++) {
            int pr = tid + r2 * 256;
            int bl = pr >> 5, kc = pr & 31;
            float yi = xv[r2][0], yf = xv[r2][1], yg = xv[r2][2], yo = xv[r2][3];
#pragma unroll
            for (int s4 = 0; s4 < 4; s4++) {
                const float* gb = gs + (s4 * 16 + bl) * GS2;
                yi += gb[kc];
                yf += gb[32 + kc];
                yg += gb[64 + kc];
                yo += gb[96 + kc];
            }
            float ig = 1.f / (1.f + expf(-yi));
            float fg = 1.f / (1.f + expf(-yf));
            float gg = fmaxf(yg, 0.f);
            float og = 1.f / (1.f + expf(-yo));
            creg[r2] = fg * creg[r2] + ig * gg;
            hdst[(size_t)(p * BP + bl) * H_DIM + q * KP + kc] = __float2half_rn(og * creg[r2]);
        }
#pragma unroll
        for (int r2 = 0; r2 < 2; r2++)
#pragma unroll
            for (int g = 0; g < 4; g++) xv[r2][g] = xvn[r2][g];

        // bar gives intra-CTA happens-before for all h stores; tid0's release
        // store extends it cross-CTA.
        __syncthreads();
        if (tid == 0) st_rel(myflag, (uint32_t)(t + 1));
    }
}

// ============================================================================
// Phase 3: out[b][o] = h_final[b] . fc_w[o] + fc_b[o]; h_final = g_h[1].
// ============================================================================
__global__ __launch_bounds__(320) void fc_kernel(const float* __restrict__ fcw,
                                                 const float* __restrict__ fcb,
                                                 float* __restrict__ out) {
    int b = blockIdx.x;
    int w = threadIdx.x >> 5, lane = threadIdx.x & 31;
    const __half* h = g_h[1] + (size_t)b * H_DIM;
    float s = 0.f;
    for (int k = lane; k < H_DIM; k += 32) s += __half2float(h[k]) * fcw[w * H_DIM + k];
#pragma unroll
    for (int off = 16; off; off >>= 1) s += __shfl_down_sync(0xffffffffu, s, off);
    if (lane == 0) out[b * O_DIM + w] = s + fcb[w];
}

extern "C" void kernel_launch(void* const* d_in, const int* in_sizes, int n_in,
                              void* d_out, int out_size) {
    const float* x   = (const float*)d_in[0];
    const float* Wih = (const float*)d_in[1];
    const float* Whh = (const float*)d_in[2];
    const float* bih = (const float*)d_in[3];
    const float* bhh = (const float*)d_in[4];
    const float* fcw = (const float*)d_in[5];
    const float* fcb = (const float*)d_in[6];
    float* out = (float*)d_out;

    cudaFuncSetAttribute(xproj_kernel, cudaFuncAttributeMaxDynamicSharedMemorySize,
                         SMEM_XP_BYTES);
    cudaFuncSetAttribute(lstm_kernel, cudaFuncAttributeMaxDynamicSharedMemorySize,
                         SMEM_LSTM_BYTES);

    cvt_x_kernel<<<16384, 256>>>(x);
    cvt_w_kernel<<<512, 256>>>(Wih);
    xproj_kernel<<<dim3(16, 1024), 256, SMEM_XP_BYTES>>>(bih, bhh);
    lstm_kernel<<<NCTA, 256, SMEM_LSTM_BYTES>>>(Whh);
    fc_kernel<<<B_DIM, 320>>>(fcw, fcb, out);
}